// round 11
// baseline (speedup 1.0000x reference)
#include <cuda_runtime.h>

// N=32768, D=256, M=4, K=1024
#define DDIM  256
#define KCB   1024
#define KD    (KCB*DDIM)

// Output flat layout (float32):
//   [0, 8388608)            x_q_total  [N, D]
//   [8388608, 8388609)      loss
//   [8388609, 8519681)      indices    [N, M] (all zero)
//   [8519681, 9568257)      new_emb    (ODD offset — scalar stores)
//   [9568257, 10616833)     new_avg    (ODD offset — scalar stores)
//   [10616833, 10620929)    new_csize
#define OFF_LOSS   8388608
#define OFF_EMB    8519681
#define OFF_AVG    9568257
#define OFF_CSIZE  10616833

// Scratch
__device__ float4 g_partial4[512 * 64];  // 512 colsum blocks x 64 float4 partials
__device__ float  g_vsum[256];           // sum_i emb[i,0,:]
__device__ float  g_embsum[4 * 256];     // per-stage latent column sums
__device__ float  g_n[4];                // per-stage sum(new_csize)

// ---------------------------------------------------------------------------
// Kernel 0 (prep): block 0 -> g_vsum; block 1 -> g_n (csize totals).
__global__ void prep_kernel(const float* __restrict__ emb,
                            const float* __restrict__ csize) {
    const int t = threadIdx.x;
    if (blockIdx.x == 0) {
        const float e0 = emb[0 * KD + t];
        const float e1 = emb[1 * KD + t];
        const float e2 = emb[2 * KD + t];
        const float e3 = emb[3 * KD + t];
        g_vsum[t] = ((e0 + e1) + e2) + e3;
    } else {
        __shared__ float red[256];
        for (int i = 0; i < 4; ++i) {
            red[t] = csize[i * KCB + t] + csize[i * KCB + 256 + t]
                   + csize[i * KCB + 512 + t] + csize[i * KCB + 768 + t];
            __syncthreads();
            for (int off = 128; off > 0; off >>= 1) {
                if (t < off) red[t] += red[t + off];
                __syncthreads();
            }
            if (t == 0) g_n[i] = 0.99f * red[0] + 327.68f;
            __syncthreads();
        }
    }
}

// ---------------------------------------------------------------------------
// Kernel 1 (big fused): 8848 blocks x 256 threads.
//   [0, 512)       colsum of x (64 rows/block, float4 loads) -> g_partial4
//   [512, 8704)    x_q_total broadcast writes (float4)
//   [8704, 8832)   loss+indices zeros
//   [8832, 8848)   new_csize
// colsum blocks come first so the x read-stream starts in wave 1 and the
// partials are ready as early as possible for the stats kernel.
__global__ void big_kernel(const float* __restrict__ x,
                           const float* __restrict__ csize,
                           float* __restrict__ out) {
    const int b = blockIdx.x;
    const int t = threadIdx.x;

    if (b < 512) {
        const int c4 = t & 63;
        const int rq = t >> 6;
        const float4* p = (const float4*)x + (size_t)b * 64 * 64 + (size_t)rq * 64 + c4;
        float4 a = make_float4(0.f, 0.f, 0.f, 0.f);
        #pragma unroll 16
        for (int i = 0; i < 16; ++i) {
            float4 v = p[i * 4 * 64];
            a.x += v.x; a.y += v.y; a.z += v.z; a.w += v.w;
        }
        __shared__ float4 sh[4][64];
        sh[rq][c4] = a;
        __syncthreads();
        if (t < 128) {
            float4 u = sh[rq][c4];              // rq in {0,1} since t<128
            float4 w = sh[rq + 2][c4];
            u.x += w.x; u.y += w.y; u.z += w.z; u.w += w.w;
            sh[rq][c4] = u;
        }
        __syncthreads();
        if (t < 64) {
            float4 u = sh[0][t], w = sh[1][t];
            u.x += w.x; u.y += w.y; u.z += w.z; u.w += w.w;
            g_partial4[b * 64 + t] = u;
        }
    } else if (b < 8704) {
        __shared__ float4 sh[64];
        if (t < 64)
            sh[t] = make_float4(g_vsum[4*t], g_vsum[4*t+1], g_vsum[4*t+2], g_vsum[4*t+3]);
        __syncthreads();
        ((float4*)out)[(size_t)(b - 512) * 256 + t] = sh[t & 63];
    } else if (b < 8832) {
        const int j4 = (b - 8704) * 256 + t;            // [0, 32768)
        ((float4*)out)[2097152 + j4] = make_float4(0.f, 0.f, 0.f, 0.f);
        if (j4 == 0) out[8519680] = 0.f;                // tail scalar of indices
    } else {
        const int i = (b - 8832) * 256 + t;             // [0, 4096)
        out[OFF_CSIZE + i] = csize[i] * 0.99f + ((i & 1023) == 0 ? 327.68f : 0.f);
    }
}

// ---------------------------------------------------------------------------
// Kernel 2 (stats): 16 blocks fold 512 partials -> g_embsum (32 KB/block).
__global__ void stats_kernel(const float* __restrict__ emb) {
    const int t = threadIdx.x;
    const int cl  = t & 15;                 // column within this block's 16
    const int bc  = t >> 4;                 // partial-chunk 0..15
    const int col = blockIdx.x * 16 + cl;
    const float* gp = (const float*)g_partial4;
    float s = 0.f;
    #pragma unroll 8
    for (int r = 0; r < 32; ++r)
        s += gp[(bc * 32 + r) * 256 + col];
    __shared__ float sh[16][17];
    sh[bc][cl] = s;
    __syncthreads();
    if (t < 16) {
        float st = 0.f;
        #pragma unroll
        for (int b = 0; b < 16; ++b) st += sh[b][t];
        const int c = blockIdx.x * 16 + t;
        const float e0 = emb[0 * KD + c];
        const float e1 = emb[1 * KD + c];
        const float e2 = emb[2 * KD + c];
        const float e3 = emb[3 * KD + c];
        g_embsum[0 * 256 + c] = st;
        g_embsum[1 * 256 + c] = st - 32768.f * e0;
        g_embsum[2 * 256 + c] = st - 32768.f * (e0 + e1);
        g_embsum[3 * 256 + c] = st - 32768.f * ((e0 + e1) + e2);
    }
}

// ---------------------------------------------------------------------------
// Kernel 3: new_emb + new_avg. 1024 blocks x 256 threads.
__global__ void emb_kernel(const float* __restrict__ avg,
                           const float* __restrict__ csize,
                           float* __restrict__ out) {
    const int j4 = blockIdx.x * 256 + threadIdx.x;   // [0, 262144)
    const int i  = j4 >> 16;                         // stage
    const int k  = (j4 >> 6) & 1023;                 // code
    const int d4 = j4 & 63;

    float4 v = ((const float4*)avg)[j4];
    v.x *= 0.99f; v.y *= 0.99f; v.z *= 0.99f; v.w *= 0.99f;
    if (k == 0) {
        const float* es = &g_embsum[i * 256 + d4 * 4];
        v.x += 0.01f * es[0];
        v.y += 0.01f * es[1];
        v.z += 0.01f * es[2];
        v.w += 0.01f * es[3];
    }
    float nc = csize[i * KCB + k] * 0.99f + (k == 0 ? 327.68f : 0.f);
    const float n = g_n[i];
    const float w = (nc + 1e-5f) / (n + 1024.f * 1e-5f) * n;
    const float inv = 1.f / w;

    const int j = j4 * 4;
    float* pe = out + OFF_EMB + j;                  // odd base: STG.32
    float* pa = out + OFF_AVG + j;
    pe[0] = v.x * inv; pe[1] = v.y * inv; pe[2] = v.z * inv; pe[3] = v.w * inv;
    pa[0] = v.x;       pa[1] = v.y;       pa[2] = v.z;       pa[3] = v.w;
}

// ---------------------------------------------------------------------------
extern "C" void kernel_launch(void* const* d_in, const int* in_sizes, int n_in,
                              void* d_out, int out_size) {
    const float* x    = (const float*)d_in[0];
    const float* emb  = (const float*)d_in[1];
    const float* avg  = (const float*)d_in[2];
    const float* cs   = (const float*)d_in[3];
    float* out = (float*)d_out;

    prep_kernel<<<2, 256>>>(emb, cs);
    big_kernel<<<8848, 256>>>(x, cs, out);
    stats_kernel<<<16, 256>>>(emb);
    emb_kernel<<<1024, 256>>>(avg, cs, out);
}

// round 12
// speedup vs baseline: 1.0747x; 1.0747x over previous
#include <cuda_runtime.h>

// N=32768, D=256, M=4, K=1024
#define DDIM  256
#define KCB   1024
#define KD    (KCB*DDIM)

// Output flat layout (float32):
//   [0, 8388608)            x_q_total  [N, D]
//   [8388608, 8388609)      loss
//   [8388609, 8519681)      indices    [N, M] (all zero)
//   [8519681, 9568257)      new_emb    (ODD offset — scalar coalesced stores)
//   [9568257, 10616833)     new_avg    (ODD offset — scalar coalesced stores)
//   [10616833, 10620929)    new_csize
#define OFF_LOSS   8388608
#define OFF_EMB    8519681
#define OFF_AVG    9568257
#define OFF_CSIZE  10616833

// Scratch
__device__ float4 g_partial4[512 * 64];  // 512 colsum blocks x 64 float4 partials
__device__ float  g_vsum[256];           // sum_i emb[i,0,:]
__device__ float  g_embsum[4 * 256];     // per-stage latent column sums
__device__ float  g_n[4];                // per-stage sum(new_csize)

// ---------------------------------------------------------------------------
// Kernel 0 (prep): block 0 -> g_vsum; block 1 -> g_n (csize totals).
__global__ void prep_kernel(const float* __restrict__ emb,
                            const float* __restrict__ csize) {
    const int t = threadIdx.x;
    if (blockIdx.x == 0) {
        const float e0 = emb[0 * KD + t];
        const float e1 = emb[1 * KD + t];
        const float e2 = emb[2 * KD + t];
        const float e3 = emb[3 * KD + t];
        g_vsum[t] = ((e0 + e1) + e2) + e3;
    } else {
        __shared__ float red[256];
        for (int i = 0; i < 4; ++i) {
            red[t] = csize[i * KCB + t] + csize[i * KCB + 256 + t]
                   + csize[i * KCB + 512 + t] + csize[i * KCB + 768 + t];
            __syncthreads();
            for (int off = 128; off > 0; off >>= 1) {
                if (t < off) red[t] += red[t + off];
                __syncthreads();
            }
            if (t == 0) g_n[i] = 0.99f * red[0] + 327.68f;
            __syncthreads();
        }
    }
}

// ---------------------------------------------------------------------------
// Kernel 1 (big fused): 8848 blocks x 256 threads.
//   [0, 512)       colsum of x (64 rows/block, __ldcs float4) -> g_partial4
//   [512, 8704)    x_q_total broadcast writes (__stcs float4)
//   [8704, 8832)   loss+indices zeros
//   [8832, 8848)   new_csize
__global__ void big_kernel(const float* __restrict__ x,
                           const float* __restrict__ csize,
                           float* __restrict__ out) {
    const int b = blockIdx.x;
    const int t = threadIdx.x;

    if (b < 512) {
        const int c4 = t & 63;
        const int rq = t >> 6;
        const float4* p = (const float4*)x + (size_t)b * 64 * 64 + (size_t)rq * 64 + c4;
        float4 a = make_float4(0.f, 0.f, 0.f, 0.f);
        #pragma unroll 16
        for (int i = 0; i < 16; ++i) {
            float4 v = __ldcs(p + i * 4 * 64);
            a.x += v.x; a.y += v.y; a.z += v.z; a.w += v.w;
        }
        __shared__ float4 sh[4][64];
        sh[rq][c4] = a;
        __syncthreads();
        if (t < 128) {
            float4 u = sh[rq][c4];              // rq in {0,1} since t<128
            float4 w = sh[rq + 2][c4];
            u.x += w.x; u.y += w.y; u.z += w.z; u.w += w.w;
            sh[rq][c4] = u;
        }
        __syncthreads();
        if (t < 64) {
            float4 u = sh[0][t], w = sh[1][t];
            u.x += w.x; u.y += w.y; u.z += w.z; u.w += w.w;
            g_partial4[b * 64 + t] = u;
        }
    } else if (b < 8704) {
        __shared__ float4 sh[64];
        if (t < 64)
            sh[t] = make_float4(g_vsum[4*t], g_vsum[4*t+1], g_vsum[4*t+2], g_vsum[4*t+3]);
        __syncthreads();
        __stcs(((float4*)out) + (size_t)(b - 512) * 256 + t, sh[t & 63]);
    } else if (b < 8832) {
        const int j4 = (b - 8704) * 256 + t;            // [0, 32768)
        __stcs(((float4*)out) + 2097152 + j4, make_float4(0.f, 0.f, 0.f, 0.f));
        if (j4 == 0) out[8519680] = 0.f;                // tail scalar of indices
    } else {
        const int i = (b - 8832) * 256 + t;             // [0, 4096)
        out[OFF_CSIZE + i] = csize[i] * 0.99f + ((i & 1023) == 0 ? 327.68f : 0.f);
    }
}

// ---------------------------------------------------------------------------
// Kernel 2 (stats): 16 blocks fold 512 partials -> g_embsum (32 KB/block).
__global__ void stats_kernel(const float* __restrict__ emb) {
    const int t = threadIdx.x;
    const int cl  = t & 15;                 // column within this block's 16
    const int bc  = t >> 4;                 // partial-chunk 0..15
    const int col = blockIdx.x * 16 + cl;
    const float* gp = (const float*)g_partial4;
    float s = 0.f;
    #pragma unroll 8
    for (int r = 0; r < 32; ++r)
        s += gp[(bc * 32 + r) * 256 + col];
    __shared__ float sh[16][17];
    sh[bc][cl] = s;
    __syncthreads();
    if (t < 16) {
        float st = 0.f;
        #pragma unroll
        for (int b = 0; b < 16; ++b) st += sh[b][t];
        const int c = blockIdx.x * 16 + t;
        const float e0 = emb[0 * KD + c];
        const float e1 = emb[1 * KD + c];
        const float e2 = emb[2 * KD + c];
        const float e3 = emb[3 * KD + c];
        g_embsum[0 * 256 + c] = st;
        g_embsum[1 * 256 + c] = st - 32768.f * e0;
        g_embsum[2 * 256 + c] = st - 32768.f * (e0 + e1);
        g_embsum[3 * 256 + c] = st - 32768.f * ((e0 + e1) + e2);
    }
}

// ---------------------------------------------------------------------------
// Kernel 3: new_emb + new_avg, COALESCED mapping. 1024 blocks x 256 threads.
// Each block handles 1024 consecutive elements = 4 full codebook rows;
// thread t handles element q*256+t for q=0..3. Every warp load/store is
// 32 consecutive 4B lanes -> full coalescing despite odd output base.
// Per q the whole block shares one code k (row), so csize is a broadcast.
__global__ void emb_kernel(const float* __restrict__ avg,
                           const float* __restrict__ csize,
                           float* __restrict__ out) {
    const int t = threadIdx.x;
    const int base = blockIdx.x * 1024;              // element base, [0, 1048576)
    const int r0 = blockIdx.x * 4;                   // global row base, [0, 4096)

    #pragma unroll
    for (int q = 0; q < 4; ++q) {
        const int r = r0 + q;                        // global row
        const int i = r >> 10;                       // stage
        const int k = r & 1023;                      // code
        const int j = base + q * 256 + t;            // element index

        float v = 0.99f * __ldcs(avg + j);
        if (k == 0) v += 0.01f * g_embsum[i * 256 + t];

        float nc = csize[r] * 0.99f + (k == 0 ? 327.68f : 0.f);
        const float n = g_n[i];
        const float w = (nc + 1e-5f) / (n + 1024.f * 1e-5f) * n;

        __stcs(out + OFF_EMB + j, v / w);
        __stcs(out + OFF_AVG + j, v);
    }
}

// ---------------------------------------------------------------------------
extern "C" void kernel_launch(void* const* d_in, const int* in_sizes, int n_in,
                              void* d_out, int out_size) {
    const float* x    = (const float*)d_in[0];
    const float* emb  = (const float*)d_in[1];
    const float* avg  = (const float*)d_in[2];
    const float* cs   = (const float*)d_in[3];
    float* out = (float*)d_out;

    prep_kernel<<<2, 256>>>(emb, cs);
    big_kernel<<<8848, 256>>>(x, cs, out);
    stats_kernel<<<16, 256>>>(emb);
    emb_kernel<<<1024, 256>>>(avg, cs, out);
}

// round 13
// speedup vs baseline: 1.3153x; 1.2239x over previous
#include <cuda_runtime.h>

// N=32768, D=256, M=4, K=1024
#define DDIM  256
#define KCB   1024
#define KD    262144              // K*D

// Output flat layout (float32):
//   [0, 8388608)            x_q_total
//   [8388608, 8388609)      loss
//   [8388609, 8519681)      indices (zeros)
//   [8519681, 9568257)      new_emb   (ODD offset)
//   [9568257, 10616833)     new_avg   (ODD offset)
//   [10616833, 10620929)    new_csize
#define OFF_EMB    8519681
#define OFF_AVG    9568257
#define OFF_CSIZE  10616833

// Scratch + sync (device globals; zero-initialized at load)
__device__ float4 g_partial4[512 * 64];
__device__ int    g_counter;   // colsum completions
__device__ int    g_done;      // waiter completions (for reset)

// Block roles:
//   [0, 512)        colsum of x
//   [512, 528)      waiters: fold partials, write k==0 emb/avg rows
//   [528, 1552)     x_q_total (1024 blocks x 8192 floats)
//   [1552, 2576)    emb/avg k!=0 (1024 blocks x 4 rows)
//   [2576, 2608)    zeros for loss+indices (32 blocks)
//   [2608, 2624)    new_csize (16 blocks)
#define B_WAIT  512
#define B_XQ    528
#define B_EMB   1552
#define B_ZERO  2576
#define B_CS    2608
#define B_TOT   2624

__global__ void __launch_bounds__(256)
fused_kernel(const float* __restrict__ x,
             const float* __restrict__ emb,
             const float* __restrict__ avg,
             const float* __restrict__ cs,
             float* __restrict__ out) {
    __shared__ float smem[1088];
    const int b = blockIdx.x;
    const int t = threadIdx.x;

    if (b < B_WAIT) {
        // ---- colsum: 64 rows of x per block, float4 streaming loads ----
        const int c4 = t & 63;
        const int rq = t >> 6;
        const float4* p = (const float4*)x + (size_t)b * 64 * 64 + (size_t)rq * 64 + c4;
        float4 a = make_float4(0.f, 0.f, 0.f, 0.f);
        #pragma unroll 16
        for (int i = 0; i < 16; ++i) {
            float4 v = __ldcs(p + i * 4 * 64);
            a.x += v.x; a.y += v.y; a.z += v.z; a.w += v.w;
        }
        float4* sh = (float4*)smem;                 // [4][64]
        sh[rq * 64 + c4] = a;
        __syncthreads();
        if (t < 128) {
            float4 u = sh[rq * 64 + c4];            // rq in {0,1}
            float4 w = sh[(rq + 2) * 64 + c4];
            u.x += w.x; u.y += w.y; u.z += w.z; u.w += w.w;
            sh[rq * 64 + c4] = u;
        }
        __syncthreads();
        if (t < 64) {
            float4 u = sh[t], w = sh[64 + t];
            u.x += w.x; u.y += w.y; u.z += w.z; u.w += w.w;
            g_partial4[b * 64 + t] = u;
            __threadfence();
        }
        __syncthreads();
        if (t == 0) atomicAdd(&g_counter, 1);

    } else if (b < B_XQ) {
        // ---- waiter: csize totals, fold partials, write k==0 rows ----
        const int w = b - B_WAIT;                   // 0..15
        float* red = smem;                          // [256]
        float* nn  = smem + 256;                    // [4]
        float* sh2 = smem + 272;                    // [16*17]
        for (int i = 0; i < 4; ++i) {
            red[t] = cs[i * KCB + t] + cs[i * KCB + 256 + t]
                   + cs[i * KCB + 512 + t] + cs[i * KCB + 768 + t];
            __syncthreads();
            for (int off = 128; off > 0; off >>= 1) {
                if (t < off) red[t] += red[t + off];
                __syncthreads();
            }
            if (t == 0) nn[i] = 0.99f * red[0] + 327.68f;
            __syncthreads();
        }
        if (t == 0) { while (atomicAdd(&g_counter, 0) < 512) { } }
        __syncthreads();
        __threadfence();
        // fold 512 partials for 16 columns: cl = t&15, chunk bc = t>>4
        const int cl = t & 15, bc = t >> 4;
        const int col = w * 16 + cl;
        const float* gp = (const float*)g_partial4;
        float s = 0.f;
        #pragma unroll 8
        for (int r = 0; r < 32; ++r)
            s += gp[(bc * 32 + r) * 256 + col];
        sh2[bc * 17 + cl] = s;
        __syncthreads();
        if (t < 16) {
            const int c = w * 16 + t;
            float st = 0.f;
            #pragma unroll
            for (int q = 0; q < 16; ++q) st += sh2[q * 17 + t];
            const float e0 = emb[0 * KD + c];
            const float e1 = emb[1 * KD + c];
            const float e2 = emb[2 * KD + c];
            float pre = 0.f;
            #pragma unroll
            for (int i = 0; i < 4; ++i) {
                const float esv = st - 32768.f * pre;
                if (i == 0) pre = e0; else if (i == 1) pre += e1; else if (i == 2) pre += e2;
                const float v = 0.99f * avg[i * KD + c] + 0.01f * esv;
                const float nc = cs[i * KCB] * 0.99f + 327.68f;
                const float n = nn[i];
                const float wg = (nc + 1e-5f) / (n + 1024.f * 1e-5f) * n;
                out[OFF_EMB + i * KD + c] = v / wg;
                out[OFF_AVG + i * KD + c] = v;
            }
        }
        __syncthreads();
        if (t == 0) {
            __threadfence();
            int old = atomicAdd(&g_done, 1);
            if (old == 15) { g_counter = 0; __threadfence(); g_done = 0; }
        }

    } else if (b < B_EMB) {
        // ---- x_q_total: broadcast sum_i emb[i,0,:]; 8192 floats/block ----
        const int bq = b - B_XQ;                    // 0..1023
        float* shv = smem;                          // [256]
        float4* sh4 = (float4*)(smem + 256);        // [64]
        shv[t] = ((emb[t] + emb[KD + t]) + emb[2 * KD + t]) + emb[3 * KD + t];
        __syncthreads();
        if (t < 64)
            sh4[t] = make_float4(shv[4*t], shv[4*t+1], shv[4*t+2], shv[4*t+3]);
        __syncthreads();
        const float4 v = sh4[t & 63];
        float4* p = (float4*)out + (size_t)bq * 2048;
        #pragma unroll
        for (int it = 0; it < 8; ++it)
            __stcs(p + it * 256 + t, v);

    } else if (b < B_ZERO) {
        // ---- emb/avg for k!=0: 4 rows per block, coalesced scalar ----
        const int bp = b - B_EMB;                   // 0..1023
        const int i  = bp >> 8;                     // stage (4 rows never cross stage)
        float* red = smem;
        float* nn  = smem + 256;
        red[t] = cs[i * KCB + t] + cs[i * KCB + 256 + t]
               + cs[i * KCB + 512 + t] + cs[i * KCB + 768 + t];
        __syncthreads();
        for (int off = 128; off > 0; off >>= 1) {
            if (t < off) red[t] += red[t + off];
            __syncthreads();
        }
        if (t == 0) nn[0] = 0.99f * red[0] + 327.68f;
        __syncthreads();
        const float n = nn[0];
        #pragma unroll
        for (int q = 0; q < 4; ++q) {
            const int r = bp * 4 + q;               // global row
            const int k = r & 1023;
            if (k == 0) continue;                   // waiters own k==0 rows
            const int j = r * 256 + t;
            const float v = 0.99f * __ldcs(avg + j);
            const float nc = cs[r] * 0.99f;
            const float wg = (nc + 1e-5f) / (n + 1024.f * 1e-5f) * n;
            __stcs(out + OFF_EMB + j, v / wg);
            __stcs(out + OFF_AVG + j, v);
        }

    } else if (b < B_CS) {
        // ---- zeros: loss + indices, 1024 float4 per block ----
        const int bz = b - B_ZERO;                  // 0..31
        float4* p = (float4*)out + 2097152 + (size_t)bz * 1024;
        const float4 z = make_float4(0.f, 0.f, 0.f, 0.f);
        #pragma unroll
        for (int it = 0; it < 4; ++it)
            __stcs(p + it * 256 + t, z);
        if (bz == 0 && t == 0) out[8519680] = 0.f;  // tail scalar of indices

    } else {
        // ---- new_csize ----
        const int i = (b - B_CS) * 256 + t;         // [0, 4096)
        out[OFF_CSIZE + i] = cs[i] * 0.99f + ((i & 1023) == 0 ? 327.68f : 0.f);
    }
}

extern "C" void kernel_launch(void* const* d_in, const int* in_sizes, int n_in,
                              void* d_out, int out_size) {
    const float* x    = (const float*)d_in[0];
    const float* emb  = (const float*)d_in[1];
    const float* avg  = (const float*)d_in[2];
    const float* cs   = (const float*)d_in[3];
    float* out = (float*)d_out;

    fused_kernel<<<B_TOT, 256>>>(x, emb, avg, cs, out);
}